// round 11
// baseline (speedup 1.0000x reference)
#include <cuda_runtime.h>
#include <cuda_bf16.h>
#include <math_constants.h>
#include <cstdint>

// ---------------- problem constants ----------------
#define NN 8192      // 2*B rows
#define BB 4096
#define DD 256
#define NP 64        // 128-row panels
#define NCTA 148     // one CTA per SM, single wave (co-residency measured R8/R10)
#define NTHR 256
#define CREF 192.0f  // fixed log2-domain exp reference (R8 analysis)

// ---------------- device scratch ----------------
__device__ __nv_bfloat16 g_hb[NN * DD];        // sqrt(2*log2e)*h in bf16
__device__ float g_ps[NP * NP * 128];          // per (rowPanel,colPanel) partial sum
__device__ float g_pos[NN];                    // positive logit (log2 units)
__device__ double g_loss;
__device__ unsigned int g_sync0, g_sync1, g_sync2;

__device__ __forceinline__ uint32_t smem_u32(const void* p) {
    uint32_t a;
    asm("{ .reg .u64 t; cvta.to.shared.u64 t, %1; cvt.u32.u64 %0, t; }" : "=r"(a) : "l"(p));
    return a;
}

__device__ __forceinline__ uint32_t ld_acq(const unsigned int* p) {
    uint32_t v;
    asm volatile("ld.acquire.gpu.b32 %0, [%1];" : "=r"(v) : "l"(p));
    return v;
}

__device__ __forceinline__ void ldsm_x4(uint32_t* r, uint32_t addr) {
    asm volatile("ldmatrix.sync.aligned.m8n8.x4.shared.b16 {%0,%1,%2,%3}, [%4];"
        : "=r"(r[0]), "=r"(r[1]), "=r"(r[2]), "=r"(r[3]) : "r"(addr));
}

__device__ __forceinline__ void mma16816(float* c, const uint32_t* a,
                                         uint32_t b0, uint32_t b1) {
    asm volatile(
        "mma.sync.aligned.m16n8k16.row.col.f32.bf16.bf16.f32 "
        "{%0,%1,%2,%3}, {%4,%5,%6,%7}, {%8,%9}, {%0,%1,%2,%3};"
        : "+f"(c[0]), "+f"(c[1]), "+f"(c[2]), "+f"(c[3])
        : "r"(a[0]), "r"(a[1]), "r"(a[2]), "r"(a[3]), "r"(b0), "r"(b1));
}

__device__ __forceinline__ void mma16816_z(float* d, const uint32_t* a,
                                           uint32_t b0, uint32_t b1) {
    asm volatile(
        "mma.sync.aligned.m16n8k16.row.col.f32.bf16.bf16.f32 "
        "{%0,%1,%2,%3}, {%4,%5,%6,%7}, {%8,%9}, {%10,%11,%12,%13};"
        : "=f"(d[0]), "=f"(d[1]), "=f"(d[2]), "=f"(d[3])
        : "r"(a[0]), "r"(a[1]), "r"(a[2]), "r"(a[3]), "r"(b0), "r"(b1),
          "f"(0.f), "f"(0.f), "f"(0.f), "f"(0.f));
}

__device__ __forceinline__ float fex2(float x) {
    float y;
    asm("ex2.approx.f32 %0, %1;" : "=f"(y) : "f"(x));
    return y;
}

#define TSWZ(r, kb) ((r) * 512 + ((kb) ^ (((r) & 7) << 4)))

__device__ __forceinline__ void load_tile(uint32_t sdst, const __nv_bfloat16* gbase,
                                          int tid) {
#pragma unroll
    for (int i = 0; i < 16; ++i) {
        int c = tid + i * 256;
        int r = c >> 5;
        int kb = (c & 31) << 4;
        uint32_t dst = sdst + TSWZ(r, kb);
        const char* src = (const char*)(gbase + (size_t)r * DD) + kb;
        asm volatile("cp.async.cg.shared.global [%0], [%1], 16;" :: "r"(dst), "l"(src));
    }
}

// smem: A 64KB | B0 64KB | B1 64KB | rowS 2KB | colS 1KB  (reused as double[256] in phase 2)
#define OFF_ROWS 196608
#define OFF_COLS (OFF_ROWS + 2048)
#define SMEM_BYTES (OFF_COLS + 1024)

__global__ __launch_bounds__(NTHR, 1) void fused_all(const float* __restrict__ h_i,
                                                     const float* __restrict__ h_j,
                                                     float* __restrict__ out) {
    extern __shared__ char smem[];
    const uint32_t sbA = smem_u32(smem);
    const uint32_t sbB0 = sbA + 65536;
    const uint32_t sbB1 = sbA + 131072;
    float* rowS = (float*)(smem + OFF_ROWS);
    float* colS = (float*)(smem + OFF_COLS);

    const int tid = threadIdx.x;
    const int lane = tid & 31;
    const int wid = tid >> 5;
    const int warp_m = wid >> 2;          // 0..1 (64-row slabs)
    const int warp_n = wid & 3;           // 0..3 (32-col slabs)
    const int cta = blockIdx.x;
    const int gid = cta * NTHR + tid;     // 0..37887

    // ================= phase 0: convert fp32 -> sqrt(2*log2e)*bf16 =================
    {
        const float s = 1.6986436f;       // sqrt(2 * log2(e))
#pragma unroll
        for (int it = 0; it < 4; ++it) {
            int v = gid + it * (NCTA * NTHR);      // 16-elem groups, 131072 total
            if (v < (NN * DD / 16)) {
                int row = v >> 4;
                int c16 = (v & 15) * 16;
                const float* src = (row < BB) ? h_i + (size_t)row * DD
                                              : h_j + (size_t)(row - BB) * DD;
                float4 x[4];
#pragma unroll
                for (int i = 0; i < 4; ++i) x[i] = *(const float4*)(src + c16 + i * 4);
                uint32_t o[8];
#pragma unroll
                for (int i = 0; i < 4; ++i) {
                    __nv_bfloat162 p0(__float2bfloat16(x[i].x * s), __float2bfloat16(x[i].y * s));
                    __nv_bfloat162 p1(__float2bfloat16(x[i].z * s), __float2bfloat16(x[i].w * s));
                    o[i * 2]     = *(uint32_t*)&p0;
                    o[i * 2 + 1] = *(uint32_t*)&p1;
                }
                uint4* dst = (uint4*)(g_hb + (size_t)row * DD + c16);
                dst[0] = make_uint4(o[0], o[1], o[2], o[3]);
                dst[1] = make_uint4(o[4], o[5], o[6], o[7]);
            }
        }
    }
    __threadfence();
    __syncthreads();
    if (tid == 0) {
        atomicAdd(&g_sync0, 1u);
        while (ld_acq(&g_sync0) < NCTA) __nanosleep(64);
    }
    __syncthreads();

    // ================= phase 1: symmetric bf16 GEMM (R8 body) =================
    const int cnt = 14 + (cta < 8 ? 1 : 0);
    int rem = cta * 14 + (cta < 8 ? cta : 8);
    int I = 0, L = NP;
    while (rem >= L) { rem -= L; ++I; --L; }
    int J = I + rem;

    load_tile(sbA, g_hb + (size_t)I * 128 * DD, tid);
    load_tile(sbB0, g_hb + (size_t)J * 128 * DD, tid);
    asm volatile("cp.async.commit_group;");

    const int lrA = (lane & 7) + ((lane >> 3) & 1) * 8;
    const int kA  = (lane >> 4) * 16;
    const int lnB = (lane & 7) + ((lane >> 4) << 3);
    const int kB  = ((lane >> 3) & 1) * 16;
    const int rquad = lane >> 2;
    const int cquad = (lane & 3) * 2;

    for (int t = 0; t < cnt; ++t) {
        const bool last = (t == cnt - 1);
        int In = I, Jn = J + 1;
        if (Jn == NP) { In = I + 1; Jn = In; }

        const uint32_t sbB = (t & 1) ? sbB1 : sbB0;
        if (!last) {
            load_tile((t & 1) ? sbB0 : sbB1, g_hb + (size_t)Jn * 128 * DD, tid);
            asm volatile("cp.async.commit_group;");
            asm volatile("cp.async.wait_group 1;");
        } else {
            asm volatile("cp.async.wait_group 0;");
        }
        __syncthreads();

        float c[4][4][4];
#pragma unroll
        for (int ks = 0; ks < 16; ++ks) {
            uint32_t a[4][4], b[2][4];
#pragma unroll
            for (int mt = 0; mt < 4; ++mt)
                ldsm_x4(a[mt], sbA + TSWZ(warp_m * 64 + mt * 16 + lrA, ks * 32 + kA));
#pragma unroll
            for (int p = 0; p < 2; ++p)
                ldsm_x4(b[p], sbB + TSWZ(warp_n * 32 + p * 16 + lnB, ks * 32 + kB));
#pragma unroll
            for (int mt = 0; mt < 4; ++mt)
#pragma unroll
                for (int nt = 0; nt < 4; ++nt) {
                    if (ks == 0)
                        mma16816_z(c[mt][nt], a[mt],
                                   b[nt >> 1][(nt & 1) * 2], b[nt >> 1][(nt & 1) * 2 + 1]);
                    else
                        mma16816(c[mt][nt], a[mt],
                                 b[nt >> 1][(nt & 1) * 2], b[nt >> 1][(nt & 1) * 2 + 1]);
                }
        }

        const bool diagT = (J == I);
        const bool posT  = (J == I + NP / 2);

        if (diagT | posT) {
#pragma unroll
            for (int mt = 0; mt < 4; ++mt)
#pragma unroll
                for (int jj = 0; jj < 2; ++jj) {
                    const int rloc = warp_m * 64 + mt * 16 + rquad + jj * 8;
#pragma unroll
                    for (int nt = 0; nt < 4; ++nt)
#pragma unroll
                        for (int jc = 0; jc < 2; ++jc) {
                            const int cloc = warp_n * 32 + nt * 8 + cquad + jc;
                            if (cloc == rloc) {
                                float v = c[mt][nt][jj * 2 + jc];
                                if (posT) {
                                    g_pos[I * 128 + rloc] = v;
                                    g_pos[J * 128 + rloc] = v;
                                } else {
                                    c[mt][nt][jj * 2 + jc] = -CUDART_INF_F;
                                }
                            }
                        }
                }
        }

#pragma unroll
        for (int mt = 0; mt < 4; ++mt)
#pragma unroll
            for (int nt = 0; nt < 4; ++nt)
#pragma unroll
                for (int k = 0; k < 4; ++k)
                    c[mt][nt][k] = fex2(c[mt][nt][k] - CREF);

#pragma unroll
        for (int mt = 0; mt < 4; ++mt)
#pragma unroll
            for (int jj = 0; jj < 2; ++jj) {
                float s = 0.f;
#pragma unroll
                for (int nt = 0; nt < 4; ++nt)
#pragma unroll
                    for (int jc = 0; jc < 2; ++jc)
                        s += c[mt][nt][jj * 2 + jc];
                s += __shfl_xor_sync(0xffffffffu, s, 1);
                s += __shfl_xor_sync(0xffffffffu, s, 2);
                if ((lane & 3) == 0) {
                    const int rloc = warp_m * 64 + mt * 16 + rquad + jj * 8;
                    rowS[warp_n * 128 + rloc] = s;
                }
            }

        if (!diagT) {
#pragma unroll
            for (int nt = 0; nt < 4; ++nt)
#pragma unroll
                for (int jc = 0; jc < 2; ++jc) {
                    float cs = 0.f;
#pragma unroll
                    for (int mt = 0; mt < 4; ++mt)
#pragma unroll
                        for (int jj = 0; jj < 2; ++jj)
                            cs += c[mt][nt][jj * 2 + jc];
                    cs += __shfl_xor_sync(0xffffffffu, cs, 4);
                    cs += __shfl_xor_sync(0xffffffffu, cs, 8);
                    cs += __shfl_xor_sync(0xffffffffu, cs, 16);
                    if (lane < 4) {
                        const int cloc = warp_n * 32 + nt * 8 + (lane & 3) * 2 + jc;
                        colS[warp_m * 128 + cloc] = cs;
                    }
                }
        }
        __syncthreads();

        if (tid < 128) {
            g_ps[((size_t)I * NP + J) * 128 + tid] =
                rowS[tid] + rowS[128 + tid] + rowS[256 + tid] + rowS[384 + tid];
        } else if (!diagT) {
            const int cl = tid - 128;
            g_ps[((size_t)J * NP + I) * 128 + cl] = colS[cl] + colS[128 + cl];
        }

        if (!last && In != I) {
            load_tile(sbA, g_hb + (size_t)In * 128 * DD, tid);
            asm volatile("cp.async.commit_group;");
        }
        __syncthreads();
        I = In; J = Jn;
    }

    // ================= phase 2: distributed finalize =================
    __threadfence();
    __syncthreads();
    if (tid == 0) {
        atomicAdd(&g_sync1, 1u);
        while (ld_acq(&g_sync1) < NCTA) __nanosleep(64);
    }
    __syncthreads();

    double* red = (double*)smem;   // GEMM smem free now
    double val = 0.0;
    if (cta < 32) {                // 32*256 = 8192 rows
        const int row = cta * NTHR + tid;
        const int R = row >> 7;
        const int rl = row & 127;
        const float* ps = g_ps + (size_t)R * NP * 128 + rl;
        float S = 0.f;
#pragma unroll 8
        for (int cc = 0; cc < NP; ++cc) S += ps[cc * 128];
        val = (double)((CREF + __log2f(S) - g_pos[row]) * 0.69314718055994531);
    }
    red[tid] = val;
    __syncthreads();
    for (int s = 128; s > 0; s >>= 1) {
        if (tid < s) red[tid] += red[tid + s];
        __syncthreads();
    }
    if (tid == 0) {
        if (cta < 32) atomicAdd(&g_loss, red[0]);
        __threadfence();
        unsigned int old = atomicAdd(&g_sync2, 1u);
        if (old == NCTA - 1) {     // last CTA: emit + reset for next replay
            __threadfence();
            out[0] = (float)(g_loss / (double)NN);
            g_loss = 0.0;
            g_sync0 = 0; g_sync1 = 0; g_sync2 = 0;
        }
    }
}

extern "C" void kernel_launch(void* const* d_in, const int* in_sizes, int n_in,
                              void* d_out, int out_size) {
    const float* h_i = (const float*)d_in[0];
    const float* h_j = (const float*)d_in[1];
    (void)in_sizes; (void)n_in; (void)out_size;

    static bool attr_set = false;
    if (!attr_set) {
        cudaFuncSetAttribute(fused_all, cudaFuncAttributeMaxDynamicSharedMemorySize,
                             SMEM_BYTES);
        attr_set = true;
    }

    fused_all<<<NCTA, NTHR, SMEM_BYTES>>>(h_i, h_j, (float*)d_out);
}

// round 12
// speedup vs baseline: 1.0565x; 1.0565x over previous
#include <cuda_runtime.h>
#include <cuda_bf16.h>
#include <math_constants.h>
#include <cstdint>

// ---------------- problem constants ----------------
#define NN 8192      // 2*B rows
#define BB 4096
#define DD 256
#define NP 64        // 128-row panels
#define NCTA 148     // 148 CTAs; 2080 = 148*14 + 8 upper-tri tiles
#define CREF 192.0f  // fixed log2-domain exp reference (R8 analysis)

// ---------------- device scratch ----------------
__device__ __nv_bfloat16 g_hb[NN * DD];        // sqrt(2*log2e)*h in bf16
__device__ float g_ps[NP * NP * 128];          // per (rowPanel,colPanel) partial sum
__device__ float g_pos[NN];                    // positive logit minus CREF (log2 units)
__device__ double g_part[32];
__device__ unsigned int g_cnt;

__device__ __forceinline__ uint32_t smem_u32(const void* p) {
    uint32_t a;
    asm("{ .reg .u64 t; cvta.to.shared.u64 t, %1; cvt.u32.u64 %0, t; }" : "=r"(a) : "l"(p));
    return a;
}

__device__ __forceinline__ void ldsm_x4(uint32_t* r, uint32_t addr) {
    asm volatile("ldmatrix.sync.aligned.m8n8.x4.shared.b16 {%0,%1,%2,%3}, [%4];"
        : "=r"(r[0]), "=r"(r[1]), "=r"(r[2]), "=r"(r[3]) : "r"(addr));
}

__device__ __forceinline__ void mma16816(float* c, const uint32_t* a,
                                         uint32_t b0, uint32_t b1) {
    asm volatile(
        "mma.sync.aligned.m16n8k16.row.col.f32.bf16.bf16.f32 "
        "{%0,%1,%2,%3}, {%4,%5,%6,%7}, {%8,%9}, {%0,%1,%2,%3};"
        : "+f"(c[0]), "+f"(c[1]), "+f"(c[2]), "+f"(c[3])
        : "r"(a[0]), "r"(a[1]), "r"(a[2]), "r"(a[3]), "r"(b0), "r"(b1));
}

// d = a*b + (-CREF): folds the exp reference into the accumulator init.
__device__ __forceinline__ void mma16816_c(float* d, const uint32_t* a,
                                           uint32_t b0, uint32_t b1, float cinit) {
    asm volatile(
        "mma.sync.aligned.m16n8k16.row.col.f32.bf16.bf16.f32 "
        "{%0,%1,%2,%3}, {%4,%5,%6,%7}, {%8,%9}, {%10,%11,%12,%13};"
        : "=f"(d[0]), "=f"(d[1]), "=f"(d[2]), "=f"(d[3])
        : "r"(a[0]), "r"(a[1]), "r"(a[2]), "r"(a[3]), "r"(b0), "r"(b1),
          "f"(cinit), "f"(cinit), "f"(cinit), "f"(cinit));
}

__device__ __forceinline__ float fex2(float x) {
    float y;
    asm("ex2.approx.f32 %0, %1;" : "=f"(y) : "f"(x));
    return y;
}

#define TSWZ(r, kb) ((r) * 512 + ((kb) ^ (((r) & 7) << 4)))

__device__ __forceinline__ void load_tile(uint32_t sdst, const __nv_bfloat16* gbase,
                                          int tid) {
#pragma unroll
    for (int i = 0; i < 16; ++i) {
        int c = tid + i * 256;
        int r = c >> 5;
        int kb = (c & 31) << 4;
        uint32_t dst = sdst + TSWZ(r, kb);
        const char* src = (const char*)(gbase + (size_t)r * DD) + kb;
        asm volatile("cp.async.cg.shared.global [%0], [%1], 16;" :: "r"(dst), "l"(src));
    }
}

// ---------------- kernel 0: fp32 -> sqrt(2*log2e)*bf16 ----------------
__global__ __launch_bounds__(256) void convert_bf16(const float* __restrict__ h_i,
                                                    const float* __restrict__ h_j) {
    int v = blockIdx.x * 256 + threadIdx.x;   // 0..524287
    int row = v >> 6;
    int c4 = v & 63;
    const float* src = (row < BB) ? h_i + (size_t)row * DD : h_j + (size_t)(row - BB) * DD;
    float4 x = *(const float4*)(src + c4 * 4);
    const float s = 1.6986436f;               // sqrt(2 * log2(e))
    __nv_bfloat162 p0 = __nv_bfloat162(__float2bfloat16(x.x * s), __float2bfloat16(x.y * s));
    __nv_bfloat162 p1 = __nv_bfloat162(__float2bfloat16(x.z * s), __float2bfloat16(x.w * s));
    uint2* dst = (uint2*)(g_hb + (size_t)row * DD + c4 * 4);
    uint2 w;
    w.x = *(uint32_t*)&p0;
    w.y = *(uint32_t*)&p1;
    *dst = w;
}

// ---------------- kernel 1: symmetric bf16 GEMM, 1 barrier/tile, deferred merge ----
// smem: A 64KB | B0 64KB | B1 64KB | rowS[2][512] 4KB | colS[2][256] 2KB
#define OFF_ROWS 196608
#define OFF_COLS (OFF_ROWS + 4096)
#define SMEM_BYTES (OFF_COLS + 2048)

__global__ __launch_bounds__(256, 1) void gemm_lse_sym() {
    extern __shared__ char smem[];
    const uint32_t sbA = smem_u32(smem);
    const uint32_t sbB0 = sbA + 65536;
    const uint32_t sbB1 = sbA + 131072;
    float* rowS = (float*)(smem + OFF_ROWS);   // [parity][4 slabs][128]
    float* colS = (float*)(smem + OFF_COLS);   // [parity][2 slabs][128]

    const int tid = threadIdx.x;
    const int lane = tid & 31;
    const int wid = tid >> 5;
    const int warp_m = wid >> 2;
    const int warp_n = wid & 3;

    // per-CTA contiguous range of upper-tri tiles (2080 = 148*14 + 8)
    const int cta = blockIdx.x;
    const int cnt = 14 + (cta < 8 ? 1 : 0);
    int rem = cta * 14 + (cta < 8 ? cta : 8);
    int I = 0, L = NP;
    while (rem >= L) { rem -= L; ++I; --L; }
    int J = I + rem;

    load_tile(sbA, g_hb + (size_t)I * 128 * DD, tid);
    load_tile(sbB0, g_hb + (size_t)J * 128 * DD, tid);
    asm volatile("cp.async.commit_group;");

    const int lrA = (lane & 7) + ((lane >> 3) & 1) * 8;
    const int kA  = (lane >> 4) * 16;
    const int lnB = (lane & 7) + ((lane >> 4) << 3);
    const int kB  = ((lane >> 3) & 1) * 16;
    const int rquad = lane >> 2;
    const int cquad = (lane & 3) * 2;

    int Ip = 0, Jp = 0;        // previous-tile coords
    bool diagPrev = true;

    for (int t = 0; t < cnt; ++t) {
        const bool last = (t == cnt - 1);
        int In = I, Jn = J + 1;
        if (Jn == NP) { In = I + 1; Jn = In; }

        const uint32_t sbB = (t & 1) ? sbB1 : sbB0;
        if (!last) {
            load_tile((t & 1) ? sbB0 : sbB1, g_hb + (size_t)Jn * 128 * DD, tid);
            asm volatile("cp.async.commit_group;");
            asm volatile("cp.async.wait_group 1;");
        } else {
            asm volatile("cp.async.wait_group 0;");
        }
        __syncthreads();   // the single per-tile barrier

        // ---- deferred merge of tile t-1 (parity (t-1)&1), in the MMA shadow ----
        if (t > 0) {
            const float* rS = rowS + ((t - 1) & 1) * 512;
            const float* cS = colS + ((t - 1) & 1) * 256;
            if (tid < 128) {
                g_ps[((size_t)Ip * NP + Jp) * 128 + tid] =
                    rS[tid] + rS[128 + tid] + rS[256 + tid] + rS[384 + tid];
            } else if (!diagPrev) {
                const int cl = tid - 128;
                g_ps[((size_t)Jp * NP + Ip) * 128 + cl] = cS[cl] + cS[128 + cl];
            }
        }

        float c[4][4][4];
#pragma unroll
        for (int ks = 0; ks < 16; ++ks) {
            uint32_t a[4][4], b[2][4];
#pragma unroll
            for (int mt = 0; mt < 4; ++mt)
                ldsm_x4(a[mt], sbA + TSWZ(warp_m * 64 + mt * 16 + lrA, ks * 32 + kA));
#pragma unroll
            for (int p = 0; p < 2; ++p)
                ldsm_x4(b[p], sbB + TSWZ(warp_n * 32 + p * 16 + lnB, ks * 32 + kB));
#pragma unroll
            for (int mt = 0; mt < 4; ++mt)
#pragma unroll
                for (int nt = 0; nt < 4; ++nt) {
                    if (ks == 0)
                        mma16816_c(c[mt][nt], a[mt],
                                   b[nt >> 1][(nt & 1) * 2], b[nt >> 1][(nt & 1) * 2 + 1],
                                   -CREF);
                    else
                        mma16816(c[mt][nt], a[mt],
                                 b[nt >> 1][(nt & 1) * 2], b[nt >> 1][(nt & 1) * 2 + 1]);
                }
        }

        const bool diagT = (J == I);
        const bool posT  = (J == I + NP / 2);

        if (diagT | posT) {
#pragma unroll
            for (int mt = 0; mt < 4; ++mt)
#pragma unroll
                for (int jj = 0; jj < 2; ++jj) {
                    const int rloc = warp_m * 64 + mt * 16 + rquad + jj * 8;
#pragma unroll
                    for (int nt = 0; nt < 4; ++nt)
#pragma unroll
                        for (int jc = 0; jc < 2; ++jc) {
                            const int cloc = warp_n * 32 + nt * 8 + cquad + jc;
                            if (cloc == rloc) {
                                float v = c[mt][nt][jj * 2 + jc];
                                if (posT) {
                                    g_pos[I * 128 + rloc] = v;   // stores pos - CREF
                                    g_pos[J * 128 + rloc] = v;
                                } else {
                                    c[mt][nt][jj * 2 + jc] = -CUDART_INF_F;
                                }
                            }
                        }
                }
        }

        // accumulators already hold v - CREF: exp is a bare ex2
#pragma unroll
        for (int mt = 0; mt < 4; ++mt)
#pragma unroll
            for (int nt = 0; nt < 4; ++nt)
#pragma unroll
                for (int k = 0; k < 4; ++k)
                    c[mt][nt][k] = fex2(c[mt][nt][k]);

        float* rS = rowS + (t & 1) * 512;
        float* cS = colS + (t & 1) * 256;

#pragma unroll
        for (int mt = 0; mt < 4; ++mt)
#pragma unroll
            for (int jj = 0; jj < 2; ++jj) {
                float s = 0.f;
#pragma unroll
                for (int nt = 0; nt < 4; ++nt)
#pragma unroll
                    for (int jc = 0; jc < 2; ++jc)
                        s += c[mt][nt][jj * 2 + jc];
                s += __shfl_xor_sync(0xffffffffu, s, 1);
                s += __shfl_xor_sync(0xffffffffu, s, 2);
                if ((lane & 3) == 0) {
                    const int rloc = warp_m * 64 + mt * 16 + rquad + jj * 8;
                    rS[warp_n * 128 + rloc] = s;
                }
            }

        if (!diagT) {
#pragma unroll
            for (int nt = 0; nt < 4; ++nt)
#pragma unroll
                for (int jc = 0; jc < 2; ++jc) {
                    float cs = 0.f;
#pragma unroll
                    for (int mt = 0; mt < 4; ++mt)
#pragma unroll
                        for (int jj = 0; jj < 2; ++jj)
                            cs += c[mt][nt][jj * 2 + jc];
                    cs += __shfl_xor_sync(0xffffffffu, cs, 4);
                    cs += __shfl_xor_sync(0xffffffffu, cs, 8);
                    cs += __shfl_xor_sync(0xffffffffu, cs, 16);
                    if (lane < 4) {
                        const int cloc = warp_n * 32 + nt * 8 + (lane & 3) * 2 + jc;
                        cS[warp_m * 128 + cloc] = cs;
                    }
                }
        }

        // A-panel advance (rare): needs all warps past this tile's ldsm
        if (!last && In != I) {
            __syncthreads();
            load_tile(sbA, g_hb + (size_t)In * 128 * DD, tid);
            asm volatile("cp.async.commit_group;");
        }
        Ip = I; Jp = J; diagPrev = diagT;
        I = In; J = Jn;
    }

    // final tile's merge
    __syncthreads();
    {
        const float* rS = rowS + ((cnt - 1) & 1) * 512;
        const float* cS = colS + ((cnt - 1) & 1) * 256;
        if (tid < 128) {
            g_ps[((size_t)Ip * NP + Jp) * 128 + tid] =
                rS[tid] + rS[128 + tid] + rS[256 + tid] + rS[384 + tid];
        } else if (!diagPrev) {
            const int cl = tid - 128;
            g_ps[((size_t)Jp * NP + Ip) * 128 + cl] = cS[cl] + cS[128 + cl];
        }
    }
}

// ---------------- fused finalize: per-row lse - pos, chip-wide double sum ----------
__global__ __launch_bounds__(256) void finalize_all(float* __restrict__ out) {
    __shared__ double red[256];
    __shared__ int s_last;
    const int tid = threadIdx.x;
    const int row = blockIdx.x * 256 + tid;
    const int R = row >> 7;
    const int rl = row & 127;
    const float* ps = g_ps + (size_t)R * NP * 128 + rl;
    float S = 0.f;
#pragma unroll 8
    for (int c = 0; c < NP; ++c) S += ps[c * 128];
    // g_pos holds (pos - CREF); S sums 2^(v - CREF): CREF cancels.
    red[tid] = (double)((__log2f(S) - g_pos[row]) * 0.69314718055994531f);
    __syncthreads();
    for (int s = 128; s > 0; s >>= 1) {
        if (tid < s) red[tid] += red[tid + s];
        __syncthreads();
    }
    if (tid == 0) {
        g_part[blockIdx.x] = red[0];
        __threadfence();
        unsigned int old = atomicAdd(&g_cnt, 1u);
        s_last = (((old + 1) & 31) == 0);
    }
    __syncthreads();
    if (s_last && tid < 32) {
        double v = g_part[tid];
#pragma unroll
        for (int off = 16; off > 0; off >>= 1)
            v += __shfl_down_sync(0xffffffffu, v, off);
        if (tid == 0) out[0] = (float)(v / (double)NN);
    }
}

extern "C" void kernel_launch(void* const* d_in, const int* in_sizes, int n_in,
                              void* d_out, int out_size) {
    const float* h_i = (const float*)d_in[0];
    const float* h_j = (const float*)d_in[1];
    (void)in_sizes; (void)n_in; (void)out_size;

    static bool attr_set = false;
    if (!attr_set) {
        cudaFuncSetAttribute(gemm_lse_sym, cudaFuncAttributeMaxDynamicSharedMemorySize,
                             SMEM_BYTES);
        attr_set = true;
    }

    convert_bf16<<<2048, 256>>>(h_i, h_j);
    gemm_lse_sym<<<NCTA, 256, SMEM_BYTES>>>();
    finalize_all<<<32, 256>>>((float*)d_out);
}